// round 4
// baseline (speedup 1.0000x reference)
#include <cuda_runtime.h>

#define NN 50000
#define NE 800000
#define FD 64

// ---------------- scratch (static device globals; no runtime alloc) ----------------
__device__ float g_deg[NN];
__device__ float g_dinv[NN];
__device__ int   g_cnt[NN];
__device__ int   g_off[NN + 1];
__device__ int   g_cur[NN];
__device__ int   g_ss[NE];     // src ids sorted by dst
__device__ float g_sw[NE];     // combined edge weights sorted by dst
__device__ __align__(16) float g_tx1[NN * FD];
__device__ __align__(16) float g_s2[NN * FD];
__device__ __align__(16) float g_wc[7 * FD * FD];   // combined weights, [mat][k][f]
__device__ float g_bias[3 * FD];                    // bz, bh, blin

// ---------------- f32x2 packed helpers (sm_103a dual-fp32 datapath) ----------------
__device__ __forceinline__ unsigned long long dup2(float a) {
    unsigned long long r;
    asm("mov.b64 %0, {%1, %1};" : "=l"(r) : "f"(a));
    return r;
}
__device__ __forceinline__ void fma2(unsigned long long& d, unsigned long long a,
                                     unsigned long long b) {
    asm("fma.rn.f32x2 %0, %1, %2, %0;" : "+l"(d) : "l"(a), "l"(b));
}
__device__ __forceinline__ void unpk2(unsigned long long v, float& x, float& y) {
    asm("mov.b64 {%0, %1}, %2;" : "=f"(x), "=f"(y) : "l"(v));
}

// ---------------- CSR build ----------------
__global__ void k_zero() {
    int i = blockIdx.x * blockDim.x + threadIdx.x;
    if (i < NN) { g_deg[i] = 0.f; g_cnt[i] = 0; }
}

__global__ void k_hist(const int* __restrict__ src, const int* __restrict__ dst,
                       const float* __restrict__ ew) {
    int e = blockIdx.x * blockDim.x + threadIdx.x;
    if (e < NE) {
        atomicAdd(&g_deg[src[e]], ew[e]);
        atomicAdd(&g_cnt[dst[e]], 1);
    }
}

// dinv + weight combining + bias combining
__global__ void k_prep(const float* __restrict__ Wxz, const float* __restrict__ bxz,
                       const float* __restrict__ bhz,
                       const float* __restrict__ Wxh, const float* __restrict__ bxh,
                       const float* __restrict__ bhh,
                       const float* __restrict__ Wlin, const float* __restrict__ blin) {
    int i = blockIdx.x * blockDim.x + threadIdx.x;
    if (i < NN) { float d = g_deg[i]; g_dinv[i] = (d > 0.f) ? rsqrtf(d) : 0.f; }
    if (i < FD * FD) {
        // Tx2 = 2*S2 - Tx0  =>  fold into W0' = W0 - W2, W2' = 2*W2
        g_wc[0 * 4096 + i] = Wxz[i] - Wxz[2 * 4096 + i];
        g_wc[1 * 4096 + i] = Wxz[4096 + i];
        g_wc[2 * 4096 + i] = 2.f * Wxz[2 * 4096 + i];
        g_wc[3 * 4096 + i] = Wxh[i] - Wxh[2 * 4096 + i];
        g_wc[4 * 4096 + i] = Wxh[4096 + i];
        g_wc[5 * 4096 + i] = 2.f * Wxh[2 * 4096 + i];
        g_wc[6 * 4096 + i] = Wlin[i];
    }
    if (i < FD) {
        g_bias[i]          = bxz[i] + bhz[i];   // H0=0 => cheb(H0)=b_hz
        g_bias[FD + i]     = bxh[i] + bhh[i];
        g_bias[2 * FD + i] = blin[i];
    }
}

// single-block exclusive scan over g_cnt -> g_off, g_cur
__global__ void __launch_bounds__(1024, 1) k_scan() {
    __shared__ int ssum[1024];
    const int T = 1024, C = (NN + T - 1) / T;  // 49
    int t = threadIdx.x;
    int b = t * C, e = (b + C < NN) ? b + C : NN;
    int s = 0;
    for (int i = b; i < e; i++) s += g_cnt[i];
    ssum[t] = s;
    __syncthreads();
    for (int d = 1; d < T; d <<= 1) {
        int v = (t >= d) ? ssum[t - d] : 0;
        __syncthreads();
        ssum[t] += v;
        __syncthreads();
    }
    int excl = (t == 0) ? 0 : ssum[t - 1];
    for (int i = b; i < e; i++) {
        g_off[i] = excl; g_cur[i] = excl;
        excl += g_cnt[i];
    }
    if (t == T - 1) g_off[NN] = NE;
}

__global__ void k_permute(const int* __restrict__ src, const int* __restrict__ dst,
                          const float* __restrict__ ew) {
    int e = blockIdx.x * blockDim.x + threadIdx.x;
    if (e >= NE) return;
    int s = src[e], d = dst[e];
    int p = atomicAdd(&g_cur[d], 1);
    g_ss[p] = s;
    g_sw[p] = -ew[e] * g_dinv[s] * g_dinv[d];
}

// ---------------- gather passes: half-warp (16 lanes) per dst node ----------------
// NOTE: device globals are referenced INSIDE device code (passing __device__
// symbols as host-side kernel args is invalid and was Round 3's bug).
__device__ __forceinline__ void gather_body(const float4* __restrict__ in4,
                                            float4* __restrict__ out4) {
    int t = blockIdx.x * blockDim.x + threadIdx.x;
    int node = t >> 4, lane = t & 15;
    if (node >= NN) return;
    int beg = g_off[node], end = g_off[node + 1];
    float4 a0 = make_float4(0.f, 0.f, 0.f, 0.f);
    float4 a1 = a0;
    int i = beg;
    for (; i + 1 < end; i += 2) {
        int   s0 = g_ss[i],  s1 = g_ss[i + 1];
        float w0 = g_sw[i],  w1 = g_sw[i + 1];
        float4 v0 = in4[s0 * 16 + lane];
        float4 v1 = in4[s1 * 16 + lane];
        a0.x = fmaf(w0, v0.x, a0.x); a0.y = fmaf(w0, v0.y, a0.y);
        a0.z = fmaf(w0, v0.z, a0.z); a0.w = fmaf(w0, v0.w, a0.w);
        a1.x = fmaf(w1, v1.x, a1.x); a1.y = fmaf(w1, v1.y, a1.y);
        a1.z = fmaf(w1, v1.z, a1.z); a1.w = fmaf(w1, v1.w, a1.w);
    }
    if (i < end) {
        int s0 = g_ss[i]; float w0 = g_sw[i];
        float4 v0 = in4[s0 * 16 + lane];
        a0.x = fmaf(w0, v0.x, a0.x); a0.y = fmaf(w0, v0.y, a0.y);
        a0.z = fmaf(w0, v0.z, a0.z); a0.w = fmaf(w0, v0.w, a0.w);
    }
    a0.x += a1.x; a0.y += a1.y; a0.z += a1.z; a0.w += a1.w;
    out4[node * 16 + lane] = a0;
}

__global__ void k_gather1(const float* __restrict__ x) {
    gather_body(reinterpret_cast<const float4*>(x),
                reinterpret_cast<float4*>(g_tx1));
}

__global__ void k_gather2() {
    gather_body(reinterpret_cast<const float4*>(g_tx1),
                reinterpret_cast<float4*>(g_s2));
}

// ---------------- fused dense kernel ----------------
#define SMEM_FLOATS (7 * 4096 + 192 + 64 * 192 + 64 * 64)

__global__ void __launch_bounds__(512, 1)
k_final(const float* __restrict__ x, float* __restrict__ out) {
    extern __shared__ float sm[];
    float* sW  = sm;                // 7*4096
    float* sB  = sW + 7 * 4096;    // 192
    float* sTx = sB + 192;         // 64 nodes * (Tx0|Tx1|S2) * 64
    float* sH  = sTx + 64 * 192;   // 64 nodes * 64

    const int tid = threadIdx.x;
    for (int i = tid; i < 7 * 4096; i += 512) sW[i] = g_wc[i];
    for (int i = tid; i < 192; i += 512) sB[i] = g_bias[i];

    const int warp = tid >> 5, lane = tid & 31;
    const int f = lane * 2;
    const int ngroups = (NN + 63) / 64;

    for (int g = blockIdx.x; g < ngroups; g += gridDim.x) {
        const int base = g * 64;
        for (int i = tid; i < 1024; i += 512) {
            int node = i >> 4, q = i & 15;
            int n = base + node;
            float4 a, b, c;
            if (n < NN) {
                a = reinterpret_cast<const float4*>(x)[n * 16 + q];
                b = reinterpret_cast<const float4*>(g_tx1)[n * 16 + q];
                c = reinterpret_cast<const float4*>(g_s2)[n * 16 + q];
            } else {
                a = make_float4(0.f, 0.f, 0.f, 0.f); b = a; c = a;
            }
            reinterpret_cast<float4*>(sTx)[node * 48 + q]      = a;
            reinterpret_cast<float4*>(sTx)[node * 48 + 16 + q] = b;
            reinterpret_cast<float4*>(sTx)[node * 48 + 32 + q] = c;
        }
        __syncthreads();

        unsigned long long az[4], ah[4];
        {
            unsigned long long bz = *(const unsigned long long*)&sB[f];
            unsigned long long bh = *(const unsigned long long*)&sB[64 + f];
            #pragma unroll
            for (int j = 0; j < 4; j++) { az[j] = bz; ah[j] = bh; }
        }
        const float* t = sTx + (warp * 4) * 192;

        #pragma unroll 4
        for (int k = 0; k < 64; k++) {
            unsigned long long w0 = *(const unsigned long long*)&sW[k * 64 + f];
            unsigned long long w1 = *(const unsigned long long*)&sW[4096 + k * 64 + f];
            unsigned long long w2 = *(const unsigned long long*)&sW[8192 + k * 64 + f];
            unsigned long long u0 = *(const unsigned long long*)&sW[12288 + k * 64 + f];
            unsigned long long u1 = *(const unsigned long long*)&sW[16384 + k * 64 + f];
            unsigned long long u2 = *(const unsigned long long*)&sW[20480 + k * 64 + f];
            #pragma unroll
            for (int j = 0; j < 4; j++) {
                unsigned long long a0 = dup2(t[j * 192 + k]);
                unsigned long long a1 = dup2(t[j * 192 + 64 + k]);
                unsigned long long a2 = dup2(t[j * 192 + 128 + k]);
                fma2(az[j], a0, w0);
                fma2(az[j], a1, w1);
                fma2(az[j], a2, w2);
                fma2(ah[j], a0, u0);
                fma2(ah[j], a1, u1);
                fma2(ah[j], a2, u2);
            }
        }

        #pragma unroll
        for (int j = 0; j < 4; j++) {
            int node = warp * 4 + j;
            float azx, azy, ahx, ahy;
            unpk2(az[j], azx, azy);
            unpk2(ah[j], ahx, ahy);
            float zx = 1.f / (1.f + __expf(-azx));
            float zy = 1.f / (1.f + __expf(-azy));
            float hx = 1.f - 2.f / (__expf(2.f * ahx) + 1.f);
            float hy = 1.f - 2.f / (__expf(2.f * ahy) + 1.f);
            sH[node * 64 + f]     = fmaxf((1.f - zx) * hx, 0.f);
            sH[node * 64 + f + 1] = fmaxf((1.f - zy) * hy, 0.f);
        }
        __syncthreads();

        unsigned long long o[4];
        {
            unsigned long long bl = *(const unsigned long long*)&sB[128 + f];
            #pragma unroll
            for (int j = 0; j < 4; j++) o[j] = bl;
        }
        #pragma unroll 4
        for (int k = 0; k < 64; k++) {
            unsigned long long wl = *(const unsigned long long*)&sW[6 * 4096 + k * 64 + f];
            #pragma unroll
            for (int j = 0; j < 4; j++) {
                unsigned long long hv = dup2(sH[(warp * 4 + j) * 64 + k]);
                fma2(o[j], hv, wl);
            }
        }
        #pragma unroll
        for (int j = 0; j < 4; j++) {
            int n = base + warp * 4 + j;
            if (n < NN) {
                float ox, oy;
                unpk2(o[j], ox, oy);
                out[n * 64 + f]     = ox;
                out[n * 64 + f + 1] = oy;
            }
        }
        __syncthreads();
    }
}

// ---------------- launch ----------------
extern "C" void kernel_launch(void* const* d_in, const int* in_sizes, int n_in,
                              void* d_out, int out_size) {
    const float* x    = (const float*)d_in[0];
    const int*   ei   = (const int*)d_in[1];
    const float* ew   = (const float*)d_in[2];
    const float* Wxz  = (const float*)d_in[3];
    const float* bxz  = (const float*)d_in[4];
    const float* bhz  = (const float*)d_in[6];   // W_hz unused (H0 = 0)
    const float* Wxh  = (const float*)d_in[11];
    const float* bxh  = (const float*)d_in[12];
    const float* bhh  = (const float*)d_in[14];  // W_hh unused
    const float* Wlin = (const float*)d_in[15];
    const float* blin = (const float*)d_in[16];
    float* out = (float*)d_out;

    const int* src = ei;
    const int* dst = ei + NE;

    cudaFuncSetAttribute(k_final, cudaFuncAttributeMaxDynamicSharedMemorySize,
                         SMEM_FLOATS * (int)sizeof(float));

    k_zero<<<(NN + 255) / 256, 256>>>();
    k_hist<<<(NE + 255) / 256, 256>>>(src, dst, ew);
    k_prep<<<(NN + 255) / 256, 256>>>(Wxz, bxz, bhz, Wxh, bxh, bhh, Wlin, blin);
    k_scan<<<1, 1024>>>();
    k_permute<<<(NE + 255) / 256, 256>>>(src, dst, ew);
    k_gather1<<<(NN * 16 + 255) / 256, 256>>>(x);
    k_gather2<<<(NN * 16 + 255) / 256, 256>>>();
    k_final<<<148, 512, SMEM_FLOATS * (int)sizeof(float)>>>(x, out);
}

// round 5
// speedup vs baseline: 1.5095x; 1.5095x over previous
#include <cuda_runtime.h>

#define NN 50000
#define NE 800000
#define FD 64

// ---------------- scratch (static device globals; no runtime alloc) ----------------
__device__ float g_deg[NN];
__device__ float g_dinv[NN];
__device__ int   g_cnt[NN];
__device__ int   g_off[NN];    // bucket start (arbitrary order, bump-allocated)
__device__ int   g_end[NN];    // bucket end
__device__ int   g_cur[NN];
__device__ int   g_total;
__device__ int   g_ss[NE];     // src ids bucketed by dst
__device__ float g_sw[NE];     // combined edge weights bucketed by dst
__device__ __align__(16) float g_tx1[NN * FD];
__device__ __align__(16) float g_s2[NN * FD];
__device__ __align__(16) float g_wc[7 * FD * FD];   // combined weights, [mat][k][f]
__device__ float g_bias[3 * FD];                    // bz, bh, blin

// ---------------- f32x2 packed helpers (sm_103a dual-fp32 datapath) ----------------
__device__ __forceinline__ unsigned long long dup2(float a) {
    unsigned long long r;
    asm("mov.b64 %0, {%1, %1};" : "=l"(r) : "f"(a));
    return r;
}
__device__ __forceinline__ void fma2(unsigned long long& d, unsigned long long a,
                                     unsigned long long b) {
    asm("fma.rn.f32x2 %0, %1, %2, %0;" : "+l"(d) : "l"(a), "l"(b));
}
__device__ __forceinline__ void unpk2(unsigned long long v, float& x, float& y) {
    asm("mov.b64 {%0, %1}, %2;" : "=f"(x), "=f"(y) : "l"(v));
}

// ---------------- CSR build ----------------
__global__ void k_zero() {
    int i = blockIdx.x * blockDim.x + threadIdx.x;
    if (i < NN) { g_deg[i] = 0.f; g_cnt[i] = 0; }
    if (i == 0) g_total = 0;
}

__global__ void k_hist(const int* __restrict__ src, const int* __restrict__ dst,
                       const float* __restrict__ ew) {
    int e = blockIdx.x * blockDim.x + threadIdx.x;
    if (e < NE) {
        atomicAdd(&g_deg[src[e]], ew[e]);
        atomicAdd(&g_cnt[dst[e]], 1);
    }
}

// dinv + bucket-base allocation (warp-aggregated bump allocator, NO prefix scan)
// + weight combining + bias combining
__global__ void k_prep(const float* __restrict__ Wxz, const float* __restrict__ bxz,
                       const float* __restrict__ bhz,
                       const float* __restrict__ Wxh, const float* __restrict__ bxh,
                       const float* __restrict__ bhh,
                       const float* __restrict__ Wlin, const float* __restrict__ blin) {
    int i = blockIdx.x * blockDim.x + threadIdx.x;
    int lane = threadIdx.x & 31;

    // bucket allocation: warp-scan counts, one atomic per warp
    {
        int c = (i < NN) ? g_cnt[i] : 0;
        int scan = c;
        #pragma unroll
        for (int d = 1; d < 32; d <<= 1) {
            int v = __shfl_up_sync(0xFFFFFFFFu, scan, d);
            if (lane >= d) scan += v;
        }
        int warpsum = __shfl_sync(0xFFFFFFFFu, scan, 31);
        int base = 0;
        if (lane == 31 && warpsum > 0) base = atomicAdd(&g_total, warpsum);
        base = __shfl_sync(0xFFFFFFFFu, base, 31);
        if (i < NN) {
            int off = base + scan - c;
            g_off[i] = off;
            g_cur[i] = off;
            g_end[i] = off + c;
            float dg = g_deg[i];
            g_dinv[i] = (dg > 0.f) ? rsqrtf(dg) : 0.f;
        }
    }

    if (i < FD * FD) {
        // Tx2 = 2*S2 - Tx0  =>  fold into W0' = W0 - W2, W2' = 2*W2
        g_wc[0 * 4096 + i] = Wxz[i] - Wxz[2 * 4096 + i];
        g_wc[1 * 4096 + i] = Wxz[4096 + i];
        g_wc[2 * 4096 + i] = 2.f * Wxz[2 * 4096 + i];
        g_wc[3 * 4096 + i] = Wxh[i] - Wxh[2 * 4096 + i];
        g_wc[4 * 4096 + i] = Wxh[4096 + i];
        g_wc[5 * 4096 + i] = 2.f * Wxh[2 * 4096 + i];
        g_wc[6 * 4096 + i] = Wlin[i];
    }
    if (i < FD) {
        g_bias[i]          = bxz[i] + bhz[i];   // H0=0 => cheb(H0)=b_hz
        g_bias[FD + i]     = bxh[i] + bhh[i];
        g_bias[2 * FD + i] = blin[i];
    }
}

__global__ void k_permute(const int* __restrict__ src, const int* __restrict__ dst,
                          const float* __restrict__ ew) {
    int e = blockIdx.x * blockDim.x + threadIdx.x;
    if (e >= NE) return;
    int s = src[e], d = dst[e];
    int p = atomicAdd(&g_cur[d], 1);
    g_ss[p] = s;
    g_sw[p] = -ew[e] * g_dinv[s] * g_dinv[d];
}

// ---------------- gather passes: half-warp (16 lanes) per dst node ----------------
__device__ __forceinline__ void gather_body(const float4* __restrict__ in4,
                                            float4* __restrict__ out4) {
    int t = blockIdx.x * blockDim.x + threadIdx.x;
    int node = t >> 4, lane = t & 15;
    if (node >= NN) return;
    int beg = g_off[node], end = g_end[node];
    float4 a0 = make_float4(0.f, 0.f, 0.f, 0.f);
    float4 a1 = a0;
    int i = beg;
    for (; i + 1 < end; i += 2) {
        int   s0 = g_ss[i],  s1 = g_ss[i + 1];
        float w0 = g_sw[i],  w1 = g_sw[i + 1];
        float4 v0 = in4[s0 * 16 + lane];
        float4 v1 = in4[s1 * 16 + lane];
        a0.x = fmaf(w0, v0.x, a0.x); a0.y = fmaf(w0, v0.y, a0.y);
        a0.z = fmaf(w0, v0.z, a0.z); a0.w = fmaf(w0, v0.w, a0.w);
        a1.x = fmaf(w1, v1.x, a1.x); a1.y = fmaf(w1, v1.y, a1.y);
        a1.z = fmaf(w1, v1.z, a1.z); a1.w = fmaf(w1, v1.w, a1.w);
    }
    if (i < end) {
        int s0 = g_ss[i]; float w0 = g_sw[i];
        float4 v0 = in4[s0 * 16 + lane];
        a0.x = fmaf(w0, v0.x, a0.x); a0.y = fmaf(w0, v0.y, a0.y);
        a0.z = fmaf(w0, v0.z, a0.z); a0.w = fmaf(w0, v0.w, a0.w);
    }
    a0.x += a1.x; a0.y += a1.y; a0.z += a1.z; a0.w += a1.w;
    out4[node * 16 + lane] = a0;
}

__global__ void k_gather1(const float* __restrict__ x) {
    gather_body(reinterpret_cast<const float4*>(x),
                reinterpret_cast<float4*>(g_tx1));
}

__global__ void k_gather2() {
    gather_body(reinterpret_cast<const float4*>(g_tx1),
                reinterpret_cast<float4*>(g_s2));
}

// ---------------- fused dense kernel ----------------
#define SMEM_FLOATS (7 * 4096 + 192 + 64 * 192 + 64 * 64)

__global__ void __launch_bounds__(512, 1)
k_final(const float* __restrict__ x, float* __restrict__ out) {
    extern __shared__ float sm[];
    float* sW  = sm;                // 7*4096
    float* sB  = sW + 7 * 4096;    // 192
    float* sTx = sB + 192;         // 64 nodes * (Tx0|Tx1|S2) * 64
    float* sH  = sTx + 64 * 192;   // 64 nodes * 64

    const int tid = threadIdx.x;
    for (int i = tid; i < 7 * 4096; i += 512) sW[i] = g_wc[i];
    for (int i = tid; i < 192; i += 512) sB[i] = g_bias[i];

    const int warp = tid >> 5, lane = tid & 31;
    const int f = lane * 2;
    const int ngroups = (NN + 63) / 64;

    for (int g = blockIdx.x; g < ngroups; g += gridDim.x) {
        const int base = g * 64;
        for (int i = tid; i < 1024; i += 512) {
            int node = i >> 4, q = i & 15;
            int n = base + node;
            float4 a, b, c;
            if (n < NN) {
                a = reinterpret_cast<const float4*>(x)[n * 16 + q];
                b = reinterpret_cast<const float4*>(g_tx1)[n * 16 + q];
                c = reinterpret_cast<const float4*>(g_s2)[n * 16 + q];
            } else {
                a = make_float4(0.f, 0.f, 0.f, 0.f); b = a; c = a;
            }
            reinterpret_cast<float4*>(sTx)[node * 48 + q]      = a;
            reinterpret_cast<float4*>(sTx)[node * 48 + 16 + q] = b;
            reinterpret_cast<float4*>(sTx)[node * 48 + 32 + q] = c;
        }
        __syncthreads();

        unsigned long long az[4], ah[4];
        {
            unsigned long long bz = *(const unsigned long long*)&sB[f];
            unsigned long long bh = *(const unsigned long long*)&sB[64 + f];
            #pragma unroll
            for (int j = 0; j < 4; j++) { az[j] = bz; ah[j] = bh; }
        }
        const float* t = sTx + (warp * 4) * 192;

        #pragma unroll 4
        for (int k = 0; k < 64; k++) {
            unsigned long long w0 = *(const unsigned long long*)&sW[k * 64 + f];
            unsigned long long w1 = *(const unsigned long long*)&sW[4096 + k * 64 + f];
            unsigned long long w2 = *(const unsigned long long*)&sW[8192 + k * 64 + f];
            unsigned long long u0 = *(const unsigned long long*)&sW[12288 + k * 64 + f];
            unsigned long long u1 = *(const unsigned long long*)&sW[16384 + k * 64 + f];
            unsigned long long u2 = *(const unsigned long long*)&sW[20480 + k * 64 + f];
            #pragma unroll
            for (int j = 0; j < 4; j++) {
                unsigned long long a0 = dup2(t[j * 192 + k]);
                unsigned long long a1 = dup2(t[j * 192 + 64 + k]);
                unsigned long long a2 = dup2(t[j * 192 + 128 + k]);
                fma2(az[j], a0, w0);
                fma2(az[j], a1, w1);
                fma2(az[j], a2, w2);
                fma2(ah[j], a0, u0);
                fma2(ah[j], a1, u1);
                fma2(ah[j], a2, u2);
            }
        }

        #pragma unroll
        for (int j = 0; j < 4; j++) {
            int node = warp * 4 + j;
            float azx, azy, ahx, ahy;
            unpk2(az[j], azx, azy);
            unpk2(ah[j], ahx, ahy);
            float zx = 1.f / (1.f + __expf(-azx));
            float zy = 1.f / (1.f + __expf(-azy));
            float hx = 1.f - 2.f / (__expf(2.f * ahx) + 1.f);
            float hy = 1.f - 2.f / (__expf(2.f * ahy) + 1.f);
            sH[node * 64 + f]     = fmaxf((1.f - zx) * hx, 0.f);
            sH[node * 64 + f + 1] = fmaxf((1.f - zy) * hy, 0.f);
        }
        __syncthreads();

        unsigned long long o[4];
        {
            unsigned long long bl = *(const unsigned long long*)&sB[128 + f];
            #pragma unroll
            for (int j = 0; j < 4; j++) o[j] = bl;
        }
        #pragma unroll 4
        for (int k = 0; k < 64; k++) {
            unsigned long long wl = *(const unsigned long long*)&sW[6 * 4096 + k * 64 + f];
            #pragma unroll
            for (int j = 0; j < 4; j++) {
                unsigned long long hv = dup2(sH[(warp * 4 + j) * 64 + k]);
                fma2(o[j], hv, wl);
            }
        }
        #pragma unroll
        for (int j = 0; j < 4; j++) {
            int n = base + warp * 4 + j;
            if (n < NN) {
                float ox, oy;
                unpk2(o[j], ox, oy);
                out[n * 64 + f]     = ox;
                out[n * 64 + f + 1] = oy;
            }
        }
        __syncthreads();
    }
}

// ---------------- launch ----------------
extern "C" void kernel_launch(void* const* d_in, const int* in_sizes, int n_in,
                              void* d_out, int out_size) {
    const float* x    = (const float*)d_in[0];
    const int*   ei   = (const int*)d_in[1];
    const float* ew   = (const float*)d_in[2];
    const float* Wxz  = (const float*)d_in[3];
    const float* bxz  = (const float*)d_in[4];
    const float* bhz  = (const float*)d_in[6];   // W_hz unused (H0 = 0)
    const float* Wxh  = (const float*)d_in[11];
    const float* bxh  = (const float*)d_in[12];
    const float* bhh  = (const float*)d_in[14];  // W_hh unused
    const float* Wlin = (const float*)d_in[15];
    const float* blin = (const float*)d_in[16];
    float* out = (float*)d_out;

    const int* src = ei;
    const int* dst = ei + NE;

    cudaFuncSetAttribute(k_final, cudaFuncAttributeMaxDynamicSharedMemorySize,
                         SMEM_FLOATS * (int)sizeof(float));

    k_zero<<<(NN + 255) / 256, 256>>>();
    k_hist<<<(NE + 255) / 256, 256>>>(src, dst, ew);
    k_prep<<<(NN + 255) / 256, 256>>>(Wxz, bxz, bhz, Wxh, bxh, bhh, Wlin, blin);
    k_permute<<<(NE + 255) / 256, 256>>>(src, dst, ew);
    k_gather1<<<(NN * 16 + 255) / 256, 256>>>(x);
    k_gather2<<<(NN * 16 + 255) / 256, 256>>>();
    k_final<<<148, 512, SMEM_FLOATS * (int)sizeof(float)>>>(x, out);
}